// round 7
// baseline (speedup 1.0000x reference)
#include <cuda_runtime.h>
#include <cuda_fp16.h>
#include <cstdint>

#define B_   2
#define S_   2048
#define D_   768
#define H_   12
#define HD_  64
#define NTOK (B_*S_)

// fp16 staging buffers
__device__ __half g_xh[NTOK*D_];     // X fp16 [m][k]
__device__ __half g_wt[3*D_*D_];     // W^T fp16 [z][n][k]
__device__ __half g_qh[NTOK*D_];     // [bh][s][64]
__device__ __half g_kh[NTOK*D_];
__device__ __half g_vh[NTOK*D_];

#define SWZ(b) ((b) ^ (((b)>>3)&0x70))

__device__ __forceinline__ uint32_t smem_u32(const void* p){
    uint32_t a;
    asm("{ .reg .u64 t; cvta.to.shared.u64 t, %1; cvt.u32.u64 %0, t; }" : "=r"(a) : "l"(p));
    return a;
}
__device__ __forceinline__ void ldsm4(uint32_t* r, uint32_t a){
    asm volatile("ldmatrix.sync.aligned.m8n8.x4.shared.b16 {%0,%1,%2,%3}, [%4];"
        : "=r"(r[0]),"=r"(r[1]),"=r"(r[2]),"=r"(r[3]) : "r"(a));
}
__device__ __forceinline__ void ldsm4t(uint32_t* r, uint32_t a){
    asm volatile("ldmatrix.sync.aligned.m8n8.x4.trans.shared.b16 {%0,%1,%2,%3}, [%4];"
        : "=r"(r[0]),"=r"(r[1]),"=r"(r[2]),"=r"(r[3]) : "r"(a));
}
__device__ __forceinline__ void mma16816(float* d, const uint32_t* a, const uint32_t* b){
    asm volatile(
        "mma.sync.aligned.m16n8k16.row.col.f32.f16.f16.f32 "
        "{%0,%1,%2,%3}, {%4,%5,%6,%7}, {%8,%9}, {%0,%1,%2,%3};"
        : "+f"(d[0]),"+f"(d[1]),"+f"(d[2]),"+f"(d[3])
        : "r"(a[0]),"r"(a[1]),"r"(a[2]),"r"(a[3]), "r"(b[0]),"r"(b[1]));
}
__device__ __forceinline__ uint32_t packh2(float x, float y){
    __half2 h = __floats2half2_rn(x, y);
    return *(uint32_t*)&h;
}
__device__ __forceinline__ float ex2(float x){
    float y; asm("ex2.approx.ftz.f32 %0, %1;" : "=f"(y) : "f"(x)); return y;
}
__device__ __forceinline__ void cpasync16(uint32_t dst, const void* src){
    asm volatile("cp.async.cg.shared.global [%0], [%1], 16;" :: "r"(dst), "l"(src));
}
#define CP_COMMIT() asm volatile("cp.async.commit_group;" ::: "memory")
#define CP_WAIT1()  asm volatile("cp.async.wait_group 1;" ::: "memory")
#define CP_WAIT0()  asm volatile("cp.async.wait_group 0;" ::: "memory")

#define LOG2E 1.4426950408889634f
#define SCL2E 0.1803368801111437f   /* 0.125 * log2(e) */

// ============================ convert X -> fp16 ============================
__global__ __launch_bounds__(256) void convert_x(const float* __restrict__ X){
    int i = (blockIdx.x * 256 + threadIdx.x) * 4;
    float4 v = *(const float4*)(X + i);
    uint2 u;
    u.x = packh2(v.x, v.y);
    u.y = packh2(v.z, v.w);
    *(uint2*)&g_xh[i] = u;
}

// ============================ convert W -> W^T fp16 ============================
__global__ __launch_bounds__(256) void convert_w(
    const float* __restrict__ Wq, const float* __restrict__ Wk, const float* __restrict__ Wv)
{
    __shared__ float t[32][33];
    const int z = blockIdx.z;
    const float* W = (z==0) ? Wq : (z==1) ? Wk : Wv;
    __half* out = g_wt + (size_t)z * D_ * D_;
    const int n0 = blockIdx.x * 32, k0 = blockIdx.y * 32;
    const int tx = threadIdx.x, ty = threadIdx.y;   // 32 x 8
#pragma unroll
    for (int i = 0; i < 32; i += 8)
        t[ty + i][tx] = W[(size_t)(k0 + ty + i) * D_ + n0 + tx];
    __syncthreads();
#pragma unroll
    for (int i = 0; i < 32; i += 8)
        out[(size_t)(n0 + ty + i) * D_ + k0 + tx] = __float2half_rn(t[tx][ty + i]);
}

// ============================ QKV GEMM (fp16 mma.sync, 3-stage cp.async) ============================
// block tile M=128 x N=128 (2 heads), K loop 768 in chunks of 64, 3-stage ring.
// 8 warps: 4(m) x 2(n), warp tile 32x64. 2 CTAs/SM (reg cap 128).
#define GEMM_SMEM 98304

__global__ __launch_bounds__(256, 2) void qkv_gemm_h(
    const float* __restrict__ bq, const float* __restrict__ bk, const float* __restrict__ bv)
{
    extern __shared__ char sm[];
    const uint32_t sA = smem_u32(sm);            // 3 x 16KB
    const uint32_t sB = sA + 49152;              // 3 x 16KB

    const int tid = threadIdx.x, wid = tid >> 5, lane = tid & 31;
    const int z  = blockIdx.z;
    const int m0 = blockIdx.x * 128;
    const int n0 = blockIdx.y * 128;

    const __half* Wth = g_wt + (size_t)z * D_ * D_;
    const float* bias = (z==0) ? bq : (z==1) ? bk : bv;
    __half* dst = (z==0) ? g_qh : (z==1) ? g_kh : g_vh;

    const int ar = tid >> 1, aseg = (tid & 1) * 4;   // row 0..127, 4 lines of 16B

    const int wm = wid & 3, wn = wid >> 2;
    const int lrow = lane & 15, lkhi = (lane >> 4) * 16;
    const int b_n  = (lane >> 4) * 8 + (lane & 7);
    const int b_k16 = ((lane >> 3) & 1) * 16;

    float acc[2][8][4];
#pragma unroll
    for (int i = 0; i < 2; i++)
#pragma unroll
        for (int j = 0; j < 8; j++)
#pragma unroll
            for (int c = 0; c < 4; c++) acc[i][j][c] = 0.0f;

    const __half* asrc_base = g_xh + (size_t)(m0 + ar) * D_ + aseg * 8;
    const __half* bsrc_base = Wth + (size_t)(n0 + ar) * D_ + aseg * 8;

    // prologue: stages 0,1
#pragma unroll
    for (int p = 0; p < 2; p++) {
        const int k0 = p * 64;
        const uint32_t so = p * 16384;
#pragma unroll
        for (int q = 0; q < 4; q++) {
            uint32_t byte = SWZ((uint32_t)ar * 128u + (aseg + q) * 16u);
            cpasync16(sA + so + byte, asrc_base + k0 + q * 8);
            cpasync16(sB + so + byte, bsrc_base + k0 + q * 8);
        }
        CP_COMMIT();
    }

    for (int kt = 0; kt < 12; kt++) {
        if (kt < 11) CP_WAIT1(); else CP_WAIT0();
        __syncthreads();
        if (kt + 2 < 12) {
            const int k0 = (kt + 2) * 64;
            const uint32_t so = ((kt + 2) % 3) * 16384;
#pragma unroll
            for (int q = 0; q < 4; q++) {
                uint32_t byte = SWZ((uint32_t)ar * 128u + (aseg + q) * 16u);
                cpasync16(sA + so + byte, asrc_base + k0 + q * 8);
                cpasync16(sB + so + byte, bsrc_base + k0 + q * 8);
            }
            CP_COMMIT();
        }

        const uint32_t a_base = sA + (kt % 3) * 16384;
        const uint32_t b_base = sB + (kt % 3) * 16384;
#pragma unroll
        for (int ks = 0; ks < 4; ks++) {
            uint32_t a0[4], a1[4];
            ldsm4(a0, a_base + SWZ((uint32_t)(wm*32 + lrow) * 128u + ks*32 + lkhi));
            ldsm4(a1, a_base + SWZ((uint32_t)(wm*32 + 16 + lrow) * 128u + ks*32 + lkhi));
#pragma unroll
            for (int jp = 0; jp < 4; jp++) {
                uint32_t bb[4];
                ldsm4(bb, b_base + SWZ((uint32_t)(wn*64 + jp*16 + b_n) * 128u + ks*32 + b_k16));
                mma16816(acc[0][jp*2+0], a0, bb+0);
                mma16816(acc[0][jp*2+1], a0, bb+2);
                mma16816(acc[1][jp*2+0], a1, bb+0);
                mma16816(acc[1][jp*2+1], a1, bb+2);
            }
        }
    }

    // epilogue: bias add, write head-major fp16
    const int g = lane >> 2, c2 = (lane & 3) * 2;
    const int h = (n0 >> 6) + wn;                    // warp's 64-col span = one head
#pragma unroll
    for (int i = 0; i < 2; i++) {
#pragma unroll
        for (int j = 0; j < 8; j++) {
            int col = j * 8 + c2;                    // dh within head
            float bz0 = bias[h * 64 + col], bz1 = bias[h * 64 + col + 1];
            int row = m0 + wm * 32 + i * 16 + g;
            int bb = row >> 11, ss = row & 2047;
            *(__half2*)&dst[(((size_t)bb * H_ + h) * S_ + ss) * HD_ + col] =
                __floats2half2_rn(acc[i][j][0] + bz0, acc[i][j][1] + bz1);
            row += 8; bb = row >> 11; ss = row & 2047;
            *(__half2*)&dst[(((size_t)bb * H_ + h) * S_ + ss) * HD_ + col] =
                __floats2half2_rn(acc[i][j][2] + bz0, acc[i][j][3] + bz1);
        }
    }
}

// ============================ attention (fp16 mma.sync, 3-stage, 64q CTA) ============================
// block: one (b,h), 64 queries, 128 threads (4 warps x 16 rows); 16 key tiles of 128.
// 3-stage K/V/mask ring, one __syncthreads per tile. 2 CTAs/SM.
// smem: Q@0 8KB, K stages @8192 (3x16KB), V stages @57344 (3x16KB), mask @106496 (3x512B)
#define ATT_SMEM 108032

__global__ __launch_bounds__(128, 2) void attn_h(
    const float* __restrict__ mask, float* __restrict__ out)
{
    extern __shared__ char sm[];
    const uint32_t sQ = smem_u32(sm);
    const uint32_t sK = sQ + 8192;
    const uint32_t sV = sQ + 57344;
    const uint32_t sM = sQ + 106496;

    const int tid = threadIdx.x, wid = tid >> 5, lane = tid & 31;
    const int bh = blockIdx.y;
    const int b  = bh / H_;
    const int h  = bh % H_;
    const int q0 = blockIdx.x * 64;

    const __half* Qg = g_qh + (size_t)bh * S_ * HD_;
    const __half* Kg = g_kh + (size_t)bh * S_ * HD_;
    const __half* Vg = g_vh + (size_t)bh * S_ * HD_;
    const float* mrow = mask + (size_t)b * S_;

    // prologue: stages 0,1 of K/V/mask (thread t loads K/V row t: 8 lines each)
#pragma unroll
    for (int p = 0; p < 2; p++) {
        const __half* ks = Kg + (size_t)(p*128 + tid) * HD_;
        const __half* vs = Vg + (size_t)(p*128 + tid) * HD_;
        const uint32_t so = p * 16384;
#pragma unroll
        for (int q = 0; q < 8; q++) {
            uint32_t byte = SWZ((uint32_t)tid * 128u + q * 16u);
            cpasync16(sK + so + byte, ks + q * 8);
            cpasync16(sV + so + byte, vs + q * 8);
        }
        if (tid < 32) cpasync16(sM + p * 512 + tid * 16, mrow + p*128 + tid * 4);
        CP_COMMIT();
    }

    // load Q tile [64][64] swizzled (plain stores)
    {
        const int lr = tid >> 1, lseg = (tid & 1) * 4;
        const uint4* src = (const uint4*)(Qg + (size_t)(q0 + lr) * HD_);
#pragma unroll
        for (int q = 0; q < 4; q++) {
            uint4 v = src[lseg + q];
            *(uint4*)(sm + SWZ((uint32_t)lr * 128u + (lseg + q) * 16u)) = v;
        }
    }
    __syncthreads();   // Q visible

    const int lrow = lane & 15, lkhi = (lane >> 4) * 16;
    const int b_n  = (lane >> 4) * 8 + (lane & 7);
    const int b_k16 = ((lane >> 3) & 1) * 16;

    // Q fragments register-resident (warp owns rows wid*16..+15)
    uint32_t qf[4][4];
#pragma unroll
    for (int ks = 0; ks < 4; ks++)
        ldsm4(qf[ks], sQ + SWZ((uint32_t)(wid*16 + lrow) * 128u + ks*32 + lkhi));

    float o[8][4];
#pragma unroll
    for (int j = 0; j < 8; j++)
#pragma unroll
        for (int c = 0; c < 4; c++) o[j][c] = 0.0f;
    float lsum0 = 0.0f, lsum1 = 0.0f;

    const int g = lane >> 2, c2 = (lane & 3) * 2;

    for (int kt = 0; kt < 16; kt++) {
        if (kt < 15) CP_WAIT1(); else CP_WAIT0();
        __syncthreads();

        // prefetch stage kt+2 (safe: all warps passed the barrier after computing kt-1)
        if (kt + 2 < 16) {
            const int st = (kt + 2) % 3;
            const __half* ksr = Kg + (size_t)((kt+2)*128 + tid) * HD_;
            const __half* vsr = Vg + (size_t)((kt+2)*128 + tid) * HD_;
            const uint32_t so = st * 16384;
#pragma unroll
            for (int q = 0; q < 8; q++) {
                uint32_t byte = SWZ((uint32_t)tid * 128u + q * 16u);
                cpasync16(sK + so + byte, ksr + q * 8);
                cpasync16(sV + so + byte, vsr + q * 8);
            }
            if (tid < 32) cpasync16(sM + st * 512 + tid * 16, mrow + (kt+2)*128 + tid * 4);
            CP_COMMIT();
        }

        const uint32_t kb = sK + (kt % 3) * 16384;
        const uint32_t vb = sV + (kt % 3) * 16384;
        const float* maskS = (const float*)(sm + 106496 + (kt % 3) * 512);

        // scores S = Q K^T : 16 n8 tiles over 128 keys
        float sc[16][4];
#pragma unroll
        for (int t = 0; t < 16; t++)
#pragma unroll
            for (int c = 0; c < 4; c++) sc[t][c] = 0.0f;

#pragma unroll
        for (int ks = 0; ks < 4; ks++) {
#pragma unroll
            for (int jp = 0; jp < 8; jp++) {
                uint32_t bb[4];
                ldsm4(bb, kb + SWZ((uint32_t)(jp*16 + b_n) * 128u + ks*32 + b_k16));
                mma16816(sc[jp*2+0], qf[ks], bb+0);
                mma16816(sc[jp*2+1], qf[ks], bb+2);
            }
        }

        // softmax (no max subtraction): p = exp2(s*0.125*log2e + m*log2e)
        uint32_t pf[8][4];
#pragma unroll
        for (int jp = 0; jp < 8; jp++) {
            float pe[4], po[4];
            {
                int tt = jp * 2;
                float m0v = maskS[tt*8 + c2] * LOG2E, m1v = maskS[tt*8 + c2 + 1] * LOG2E;
                pe[0] = ex2(fmaf(sc[tt][0], SCL2E, m0v));
                pe[1] = ex2(fmaf(sc[tt][1], SCL2E, m1v));
                pe[2] = ex2(fmaf(sc[tt][2], SCL2E, m0v));
                pe[3] = ex2(fmaf(sc[tt][3], SCL2E, m1v));
            }
            {
                int tt = jp * 2 + 1;
                float m0v = maskS[tt*8 + c2] * LOG2E, m1v = maskS[tt*8 + c2 + 1] * LOG2E;
                po[0] = ex2(fmaf(sc[tt][0], SCL2E, m0v));
                po[1] = ex2(fmaf(sc[tt][1], SCL2E, m1v));
                po[2] = ex2(fmaf(sc[tt][2], SCL2E, m0v));
                po[3] = ex2(fmaf(sc[tt][3], SCL2E, m1v));
            }
            lsum0 += pe[0] + pe[1] + po[0] + po[1];
            lsum1 += pe[2] + pe[3] + po[2] + po[3];
            pf[jp][0] = packh2(pe[0], pe[1]);
            pf[jp][1] = packh2(pe[2], pe[3]);
            pf[jp][2] = packh2(po[0], po[1]);
            pf[jp][3] = packh2(po[2], po[3]);
        }

        // O += P @ V : k over 128 keys (8 steps), 8 d-tiles
#pragma unroll
        for (int ks2 = 0; ks2 < 8; ks2++) {
#pragma unroll
            for (int pp = 0; pp < 4; pp++) {
                uint32_t bb[4];
                uint32_t key = (uint32_t)(ks2*16 + ((lane>>3)&1)*8 + (lane&7));
                uint32_t byte = (uint32_t)(2*pp + (lane>>4)) * 16u;
                ldsm4t(bb, vb + SWZ(key * 128u + byte));
                mma16816(o[pp*2+0], pf[ks2], bb+0);
                mma16816(o[pp*2+1], pf[ks2], bb+2);
            }
        }
    }

    // reduce row sums across the 4-thread group
    lsum0 += __shfl_xor_sync(0xffffffffu, lsum0, 1);
    lsum0 += __shfl_xor_sync(0xffffffffu, lsum0, 2);
    lsum1 += __shfl_xor_sync(0xffffffffu, lsum1, 1);
    lsum1 += __shfl_xor_sync(0xffffffffu, lsum1, 2);
    const float inv0 = 1.0f / lsum0, inv1 = 1.0f / lsum1;

    const int row0 = q0 + wid * 16 + g;
    float* out0 = out + ((size_t)b * S_ + row0) * D_ + h * HD_;
    float* out1 = out + ((size_t)b * S_ + row0 + 8) * D_ + h * HD_;
#pragma unroll
    for (int j = 0; j < 8; j++) {
        int d = j * 8 + c2;
        float2 v0 = make_float2(o[j][0] * inv0, o[j][1] * inv0);
        float2 v1 = make_float2(o[j][2] * inv1, o[j][3] * inv1);
        *(float2*)&out0[d] = v0;
        *(float2*)&out1[d] = v1;
    }
}

// ============================ launch ============================
extern "C" void kernel_launch(void* const* d_in, const int* in_sizes, int n_in,
                              void* d_out, int out_size)
{
    const float* v1   = (const float*)d_in[0];
    const float* mask = (const float*)d_in[1];
    const float* Wq   = (const float*)d_in[2];
    const float* bq   = (const float*)d_in[3];
    const float* Wk   = (const float*)d_in[4];
    const float* bk   = (const float*)d_in[5];
    const float* Wv   = (const float*)d_in[6];
    const float* bv   = (const float*)d_in[7];
    float* out = (float*)d_out;

    convert_x<<<NTOK * D_ / 1024, 256>>>(v1);
    convert_w<<<dim3(D_/32, D_/32, 3), dim3(32, 8)>>>(Wq, Wk, Wv);

    cudaFuncSetAttribute(qkv_gemm_h, cudaFuncAttributeMaxDynamicSharedMemorySize, GEMM_SMEM);
    qkv_gemm_h<<<dim3(NTOK/128, D_/128, 3), 256, GEMM_SMEM>>>(bq, bk, bv);

    cudaFuncSetAttribute(attn_h, cudaFuncAttributeMaxDynamicSharedMemorySize, ATT_SMEM);
    attn_h<<<dim3(S_/64, B_*H_), 128, ATT_SMEM>>>(mask, out);
}

// round 9
// speedup vs baseline: 1.3601x; 1.3601x over previous
#include <cuda_runtime.h>
#include <cuda_fp16.h>
#include <cstdint>

#define B_   2
#define S_   2048
#define D_   768
#define H_   12
#define HD_  64
#define NTOK (B_*S_)

// fp16 staging buffers
__device__ __half g_xh[NTOK*D_];     // X fp16 [m][k]
__device__ __half g_wt[3*D_*D_];     // W^T fp16 [z][n][k]
__device__ __half g_qh[NTOK*D_];     // [bh][s][64]
__device__ __half g_kh[NTOK*D_];
__device__ __half g_vh[NTOK*D_];

#define SWZ(b) ((b) ^ (((b)>>3)&0x70))

__device__ __forceinline__ uint32_t smem_u32(const void* p){
    uint32_t a;
    asm("{ .reg .u64 t; cvta.to.shared.u64 t, %1; cvt.u32.u64 %0, t; }" : "=r"(a) : "l"(p));
    return a;
}
__device__ __forceinline__ void ldsm4(uint32_t* r, uint32_t a){
    asm volatile("ldmatrix.sync.aligned.m8n8.x4.shared.b16 {%0,%1,%2,%3}, [%4];"
        : "=r"(r[0]),"=r"(r[1]),"=r"(r[2]),"=r"(r[3]) : "r"(a));
}
__device__ __forceinline__ void ldsm4t(uint32_t* r, uint32_t a){
    asm volatile("ldmatrix.sync.aligned.m8n8.x4.trans.shared.b16 {%0,%1,%2,%3}, [%4];"
        : "=r"(r[0]),"=r"(r[1]),"=r"(r[2]),"=r"(r[3]) : "r"(a));
}
__device__ __forceinline__ void mma16816(float* d, const uint32_t* a, const uint32_t* b){
    asm volatile(
        "mma.sync.aligned.m16n8k16.row.col.f32.f16.f16.f32 "
        "{%0,%1,%2,%3}, {%4,%5,%6,%7}, {%8,%9}, {%0,%1,%2,%3};"
        : "+f"(d[0]),"+f"(d[1]),"+f"(d[2]),"+f"(d[3])
        : "r"(a[0]),"r"(a[1]),"r"(a[2]),"r"(a[3]), "r"(b[0]),"r"(b[1]));
}
__device__ __forceinline__ uint32_t packh2(float x, float y){
    __half2 h = __floats2half2_rn(x, y);
    return *(uint32_t*)&h;
}
__device__ __forceinline__ float ex2(float x){
    float y; asm("ex2.approx.ftz.f32 %0, %1;" : "=f"(y) : "f"(x)); return y;
}
__device__ __forceinline__ void cpasync16(uint32_t dst, const void* src){
    asm volatile("cp.async.cg.shared.global [%0], [%1], 16;" :: "r"(dst), "l"(src));
}
#define CP_COMMIT() asm volatile("cp.async.commit_group;" ::: "memory")
#define CP_WAIT1()  asm volatile("cp.async.wait_group 1;" ::: "memory")
#define CP_WAIT0()  asm volatile("cp.async.wait_group 0;" ::: "memory")

#define LOG2E 1.4426950408889634f
#define SCL2E 0.1803368801111437f   /* 0.125 * log2(e) */

// ============================ convert X -> fp16 ============================
__global__ __launch_bounds__(256) void convert_x(const float* __restrict__ X){
    int i = (blockIdx.x * 256 + threadIdx.x) * 4;
    float4 v = *(const float4*)(X + i);
    uint2 u;
    u.x = packh2(v.x, v.y);
    u.y = packh2(v.z, v.w);
    *(uint2*)&g_xh[i] = u;
}

// ============================ convert W -> W^T fp16 ============================
__global__ __launch_bounds__(256) void convert_w(
    const float* __restrict__ Wq, const float* __restrict__ Wk, const float* __restrict__ Wv)
{
    __shared__ float t[32][33];
    const int z = blockIdx.z;
    const float* W = (z==0) ? Wq : (z==1) ? Wk : Wv;
    __half* out = g_wt + (size_t)z * D_ * D_;
    const int n0 = blockIdx.x * 32, k0 = blockIdx.y * 32;
    const int tx = threadIdx.x, ty = threadIdx.y;   // 32 x 8
#pragma unroll
    for (int i = 0; i < 32; i += 8)
        t[ty + i][tx] = W[(size_t)(k0 + ty + i) * D_ + n0 + tx];
    __syncthreads();
#pragma unroll
    for (int i = 0; i < 32; i += 8)
        out[(size_t)(n0 + ty + i) * D_ + k0 + tx] = __float2half_rn(t[tx][ty + i]);
}

// ============================ QKV GEMM (fp16 mma.sync, 3-stage cp.async) ============================
// block tile M=128 x N=128 (2 heads), K loop 768 in chunks of 64, 3-stage ring.
// 8 warps: 4(m) x 2(n), warp tile 32x64. 2 CTAs/SM (reg cap 128).
#define GEMM_SMEM 98304

__global__ __launch_bounds__(256, 2) void qkv_gemm_h(
    const float* __restrict__ bq, const float* __restrict__ bk, const float* __restrict__ bv)
{
    extern __shared__ char sm[];
    const uint32_t sA = smem_u32(sm);            // 3 x 16KB
    const uint32_t sB = sA + 49152;              // 3 x 16KB

    const int tid = threadIdx.x, wid = tid >> 5, lane = tid & 31;
    const int z  = blockIdx.z;
    const int m0 = blockIdx.x * 128;
    const int n0 = blockIdx.y * 128;

    const __half* Wth = g_wt + (size_t)z * D_ * D_;
    const float* bias = (z==0) ? bq : (z==1) ? bk : bv;
    __half* dst = (z==0) ? g_qh : (z==1) ? g_kh : g_vh;

    const int ar = tid >> 1, aseg = (tid & 1) * 4;   // row 0..127, 4 lines of 16B

    const int wm = wid & 3, wn = wid >> 2;
    const int lrow = lane & 15, lkhi = (lane >> 4) * 16;
    const int b_n  = (lane >> 4) * 8 + (lane & 7);
    const int b_k16 = ((lane >> 3) & 1) * 16;

    float acc[2][8][4];
#pragma unroll
    for (int i = 0; i < 2; i++)
#pragma unroll
        for (int j = 0; j < 8; j++)
#pragma unroll
            for (int c = 0; c < 4; c++) acc[i][j][c] = 0.0f;

    const __half* asrc_base = g_xh + (size_t)(m0 + ar) * D_ + aseg * 8;
    const __half* bsrc_base = Wth + (size_t)(n0 + ar) * D_ + aseg * 8;

    // prologue: stages 0,1
#pragma unroll
    for (int p = 0; p < 2; p++) {
        const int k0 = p * 64;
        const uint32_t so = p * 16384;
#pragma unroll
        for (int q = 0; q < 4; q++) {
            uint32_t byte = SWZ((uint32_t)ar * 128u + (aseg + q) * 16u);
            cpasync16(sA + so + byte, asrc_base + k0 + q * 8);
            cpasync16(sB + so + byte, bsrc_base + k0 + q * 8);
        }
        CP_COMMIT();
    }

    for (int kt = 0; kt < 12; kt++) {
        if (kt < 11) CP_WAIT1(); else CP_WAIT0();
        __syncthreads();
        if (kt + 2 < 12) {
            const int k0 = (kt + 2) * 64;
            const uint32_t so = ((kt + 2) % 3) * 16384;
#pragma unroll
            for (int q = 0; q < 4; q++) {
                uint32_t byte = SWZ((uint32_t)ar * 128u + (aseg + q) * 16u);
                cpasync16(sA + so + byte, asrc_base + k0 + q * 8);
                cpasync16(sB + so + byte, bsrc_base + k0 + q * 8);
            }
            CP_COMMIT();
        }

        const uint32_t a_base = sA + (kt % 3) * 16384;
        const uint32_t b_base = sB + (kt % 3) * 16384;
#pragma unroll
        for (int ks = 0; ks < 4; ks++) {
            uint32_t a0[4], a1[4];
            ldsm4(a0, a_base + SWZ((uint32_t)(wm*32 + lrow) * 128u + ks*32 + lkhi));
            ldsm4(a1, a_base + SWZ((uint32_t)(wm*32 + 16 + lrow) * 128u + ks*32 + lkhi));
#pragma unroll
            for (int jp = 0; jp < 4; jp++) {
                uint32_t bb[4];
                ldsm4(bb, b_base + SWZ((uint32_t)(wn*64 + jp*16 + b_n) * 128u + ks*32 + b_k16));
                mma16816(acc[0][jp*2+0], a0, bb+0);
                mma16816(acc[0][jp*2+1], a0, bb+2);
                mma16816(acc[1][jp*2+0], a1, bb+0);
                mma16816(acc[1][jp*2+1], a1, bb+2);
            }
        }
    }

    // epilogue: bias add, write head-major fp16
    const int g = lane >> 2, c2 = (lane & 3) * 2;
    const int h = (n0 >> 6) + wn;                    // warp's 64-col span = one head
#pragma unroll
    for (int i = 0; i < 2; i++) {
#pragma unroll
        for (int j = 0; j < 8; j++) {
            int col = j * 8 + c2;                    // dh within head
            float bz0 = bias[h * 64 + col], bz1 = bias[h * 64 + col + 1];
            int row = m0 + wm * 32 + i * 16 + g;
            int bb = row >> 11, ss = row & 2047;
            *(__half2*)&dst[(((size_t)bb * H_ + h) * S_ + ss) * HD_ + col] =
                __floats2half2_rn(acc[i][j][0] + bz0, acc[i][j][1] + bz1);
            row += 8; bb = row >> 11; ss = row & 2047;
            *(__half2*)&dst[(((size_t)bb * H_ + h) * S_ + ss) * HD_ + col] =
                __floats2half2_rn(acc[i][j][2] + bz0, acc[i][j][3] + bz1);
        }
    }
}

// ============================ attention (fp16 mma.sync, 2-stage, half-pass softmax) ============================
// block: one (b,h), 128 queries, 256 threads (8 warps x 16 rows); 16 key tiles of 128.
// Per tile: two 64-key half-passes (scores -> exp -> PV) to halve live registers.
// 2 CTAs/SM via __launch_bounds__(256,2).
// smem: Q@0 16KB, K0@16384, K1@32768, V0@49152, V1@65536, mask0@81920, mask1@82432
#define ATT_SMEM 82944

__global__ __launch_bounds__(256, 2) void attn_h(
    const float* __restrict__ mask, float* __restrict__ out)
{
    extern __shared__ char sm[];
    const uint32_t sQ = smem_u32(sm);
    const uint32_t sK = sQ + 16384;
    const uint32_t sV = sQ + 49152;
    const uint32_t sM = sQ + 81920;

    const int tid = threadIdx.x, wid = tid >> 5, lane = tid & 31;
    const int bh = blockIdx.y;
    const int b  = bh / H_;
    const int h  = bh % H_;
    const int q0 = blockIdx.x * 128;

    const __half* Qg = g_qh + (size_t)bh * S_ * HD_;
    const __half* Kg = g_kh + (size_t)bh * S_ * HD_;
    const __half* Vg = g_vh + (size_t)bh * S_ * HD_;
    const float* mrow = mask + (size_t)b * S_;

    const int lr = tid >> 1, lseg = (tid & 1) * 4;

    // load Q tile [128][64] swizzled (plain loads, once)
    {
        const uint4* src = (const uint4*)(Qg + (size_t)(q0 + lr) * HD_);
#pragma unroll
        for (int q = 0; q < 4; q++) {
            uint4 v = src[lseg + q];
            *(uint4*)(sm + SWZ((uint32_t)lr * 128u + (lseg + q) * 16u)) = v;
        }
    }

    // prologue: stage 0 of K/V/mask
    {
        const __half* ksrc = Kg + (size_t)lr * HD_ + lseg * 8;
        const __half* vsrc = Vg + (size_t)lr * HD_ + lseg * 8;
#pragma unroll
        for (int q = 0; q < 4; q++) {
            uint32_t byte = SWZ((uint32_t)lr * 128u + (lseg + q) * 16u);
            cpasync16(sK + byte, ksrc + q * 8);
            cpasync16(sV + byte, vsrc + q * 8);
        }
        if (tid < 32) cpasync16(sM + tid * 16, mrow + tid * 4);
        CP_COMMIT();
    }
    __syncthreads();   // Q visible for ldmatrix

    const int lrow = lane & 15, lkhi = (lane >> 4) * 16;
    const int b_n  = (lane >> 4) * 8 + (lane & 7);
    const int b_k16 = ((lane >> 3) & 1) * 16;

    // Q fragments register-resident
    uint32_t qf[4][4];
#pragma unroll
    for (int ks = 0; ks < 4; ks++)
        ldsm4(qf[ks], sQ + SWZ((uint32_t)(wid*16 + lrow) * 128u + ks*32 + lkhi));

    float o[8][4];
#pragma unroll
    for (int j = 0; j < 8; j++)
#pragma unroll
        for (int c = 0; c < 4; c++) o[j][c] = 0.0f;
    float lsum0 = 0.0f, lsum1 = 0.0f;

    const int g = lane >> 2, c2 = (lane & 3) * 2;

    for (int kt = 0; kt < 16; kt++) {
        const int s = kt & 1;
        if (kt < 15) {
            const uint32_t so = (s ^ 1) * 16384;
            const __half* ksrc = Kg + (size_t)((kt+1)*128 + lr) * HD_ + lseg * 8;
            const __half* vsrc = Vg + (size_t)((kt+1)*128 + lr) * HD_ + lseg * 8;
#pragma unroll
            for (int q = 0; q < 4; q++) {
                uint32_t byte = SWZ((uint32_t)lr * 128u + (lseg + q) * 16u);
                cpasync16(sK + so + byte, ksrc + q * 8);
                cpasync16(sV + so + byte, vsrc + q * 8);
            }
            if (tid < 32) cpasync16(sM + (s ^ 1) * 512 + tid * 16, mrow + (kt+1)*128 + tid * 4);
            CP_COMMIT();
            CP_WAIT1();
        } else {
            CP_WAIT0();
        }
        __syncthreads();

        const uint32_t kb = sK + s * 16384;
        const uint32_t vb = sV + s * 16384;
        const float* maskS = (const float*)(sm + 81920 + s * 512);

        // two half-passes over the 128 keys: scores -> exp -> PV (keeps regs low)
#pragma unroll
        for (int hf = 0; hf < 2; hf++) {
            // scores for 64 keys: 8 n8-tiles
            float sc[8][4];
#pragma unroll
            for (int t = 0; t < 8; t++)
#pragma unroll
                for (int c = 0; c < 4; c++) sc[t][c] = 0.0f;

#pragma unroll
            for (int ks = 0; ks < 4; ks++) {
#pragma unroll
                for (int jp = 0; jp < 4; jp++) {
                    uint32_t bb[4];
                    ldsm4(bb, kb + SWZ((uint32_t)(hf*64 + jp*16 + b_n) * 128u + ks*32 + b_k16));
                    mma16816(sc[jp*2+0], qf[ks], bb+0);
                    mma16816(sc[jp*2+1], qf[ks], bb+2);
                }
            }

            // softmax (no max subtraction): p = exp2(s*0.125*log2e + m*log2e)
            uint32_t pf[4][4];
#pragma unroll
            for (int jp = 0; jp < 4; jp++) {
                float pe[4], po[4];
                {
                    int tt = jp * 2;
                    float m0v = maskS[hf*64 + tt*8 + c2] * LOG2E;
                    float m1v = maskS[hf*64 + tt*8 + c2 + 1] * LOG2E;
                    pe[0] = ex2(fmaf(sc[tt][0], SCL2E, m0v));
                    pe[1] = ex2(fmaf(sc[tt][1], SCL2E, m1v));
                    pe[2] = ex2(fmaf(sc[tt][2], SCL2E, m0v));
                    pe[3] = ex2(fmaf(sc[tt][3], SCL2E, m1v));
                }
                {
                    int tt = jp * 2 + 1;
                    float m0v = maskS[hf*64 + tt*8 + c2] * LOG2E;
                    float m1v = maskS[hf*64 + tt*8 + c2 + 1] * LOG2E;
                    po[0] = ex2(fmaf(sc[tt][0], SCL2E, m0v));
                    po[1] = ex2(fmaf(sc[tt][1], SCL2E, m1v));
                    po[2] = ex2(fmaf(sc[tt][2], SCL2E, m0v));
                    po[3] = ex2(fmaf(sc[tt][3], SCL2E, m1v));
                }
                lsum0 += pe[0] + pe[1] + po[0] + po[1];
                lsum1 += pe[2] + pe[3] + po[2] + po[3];
                pf[jp][0] = packh2(pe[0], pe[1]);
                pf[jp][1] = packh2(pe[2], pe[3]);
                pf[jp][2] = packh2(po[0], po[1]);
                pf[jp][3] = packh2(po[2], po[3]);
            }

            // O += P_half @ V_half : 4 k16 steps over this 64-key half, 8 d-tiles
#pragma unroll
            for (int ks2 = 0; ks2 < 4; ks2++) {
#pragma unroll
                for (int pp = 0; pp < 4; pp++) {
                    uint32_t bb[4];
                    uint32_t key = (uint32_t)(hf*64 + ks2*16 + ((lane>>3)&1)*8 + (lane&7));
                    uint32_t byte = (uint32_t)(2*pp + (lane>>4)) * 16u;
                    ldsm4t(bb, vb + SWZ(key * 128u + byte));
                    mma16816(o[pp*2+0], pf[ks2], bb+0);
                    mma16816(o[pp*2+1], pf[ks2], bb+2);
                }
            }
        }
        __syncthreads();   // everyone done with stage s before it is refilled
    }

    // reduce row sums across the 4-thread group
    lsum0 += __shfl_xor_sync(0xffffffffu, lsum0, 1);
    lsum0 += __shfl_xor_sync(0xffffffffu, lsum0, 2);
    lsum1 += __shfl_xor_sync(0xffffffffu, lsum1, 1);
    lsum1 += __shfl_xor_sync(0xffffffffu, lsum1, 2);
    const float inv0 = 1.0f / lsum0, inv1 = 1.0f / lsum1;

    const int row0 = q0 + wid * 16 + g;
    float* out0 = out + ((size_t)b * S_ + row0) * D_ + h * HD_;
    float* out1 = out + ((size_t)b * S_ + row0 + 8) * D_ + h * HD_;
#pragma unroll
    for (int j = 0; j < 8; j++) {
        int d = j * 8 + c2;
        float2 v0 = make_float2(o[j][0] * inv0, o[j][1] * inv0);
        float2 v1 = make_float2(o[j][2] * inv1, o[j][3] * inv1);
        *(float2*)&out0[d] = v0;
        *(float2*)&out1[d] = v1;
    }
}

// ============================ launch ============================
extern "C" void kernel_launch(void* const* d_in, const int* in_sizes, int n_in,
                              void* d_out, int out_size)
{
    const float* v1   = (const float*)d_in[0];
    const float* mask = (const float*)d_in[1];
    const float* Wq   = (const float*)d_in[2];
    const float* bq   = (const float*)d_in[3];
    const float* Wk   = (const float*)d_in[4];
    const float* bk   = (const float*)d_in[5];
    const float* Wv   = (const float*)d_in[6];
    const float* bv   = (const float*)d_in[7];
    float* out = (float*)d_out;

    convert_x<<<NTOK * D_ / 1024, 256>>>(v1);
    convert_w<<<dim3(D_/32, D_/32, 3), dim3(32, 8)>>>(Wq, Wk, Wv);

    cudaFuncSetAttribute(qkv_gemm_h, cudaFuncAttributeMaxDynamicSharedMemorySize, GEMM_SMEM);
    qkv_gemm_h<<<dim3(NTOK/128, D_/128, 3), 256, GEMM_SMEM>>>(bq, bk, bv);

    cudaFuncSetAttribute(attn_h, cudaFuncAttributeMaxDynamicSharedMemorySize, ATT_SMEM);
    attn_h<<<dim3(S_/128, B_*H_), 256, ATT_SMEM>>>(mask, out);
}

// round 10
// speedup vs baseline: 1.3835x; 1.0172x over previous
#include <cuda_runtime.h>
#include <cuda_fp16.h>
#include <cstdint>

#define B_   2
#define S_   2048
#define D_   768
#define H_   12
#define HD_  64
#define NTOK (B_*S_)

// fp16 staging buffers
__device__ __half g_xh[NTOK*D_];     // X fp16 [m][k]
__device__ __half g_wt[3*D_*D_];     // W^T fp16 [z][n][k]
__device__ __half g_qh[NTOK*D_];     // [bh][s][64]
__device__ __half g_kh[NTOK*D_];
__device__ __half g_vh[NTOK*D_];

#define SWZ(b) ((b) ^ (((b)>>3)&0x70))

__device__ __forceinline__ uint32_t smem_u32(const void* p){
    uint32_t a;
    asm("{ .reg .u64 t; cvta.to.shared.u64 t, %1; cvt.u32.u64 %0, t; }" : "=r"(a) : "l"(p));
    return a;
}
__device__ __forceinline__ void ldsm4(uint32_t* r, uint32_t a){
    asm volatile("ldmatrix.sync.aligned.m8n8.x4.shared.b16 {%0,%1,%2,%3}, [%4];"
        : "=r"(r[0]),"=r"(r[1]),"=r"(r[2]),"=r"(r[3]) : "r"(a));
}
__device__ __forceinline__ void ldsm4t(uint32_t* r, uint32_t a){
    asm volatile("ldmatrix.sync.aligned.m8n8.x4.trans.shared.b16 {%0,%1,%2,%3}, [%4];"
        : "=r"(r[0]),"=r"(r[1]),"=r"(r[2]),"=r"(r[3]) : "r"(a));
}
__device__ __forceinline__ void mma16816(float* d, const uint32_t* a, const uint32_t* b){
    asm volatile(
        "mma.sync.aligned.m16n8k16.row.col.f32.f16.f16.f32 "
        "{%0,%1,%2,%3}, {%4,%5,%6,%7}, {%8,%9}, {%0,%1,%2,%3};"
        : "+f"(d[0]),"+f"(d[1]),"+f"(d[2]),"+f"(d[3])
        : "r"(a[0]),"r"(a[1]),"r"(a[2]),"r"(a[3]), "r"(b[0]),"r"(b[1]));
}
__device__ __forceinline__ uint32_t packh2(float x, float y){
    __half2 h = __floats2half2_rn(x, y);
    return *(uint32_t*)&h;
}
__device__ __forceinline__ float ex2(float x){
    float y; asm("ex2.approx.ftz.f32 %0, %1;" : "=f"(y) : "f"(x)); return y;
}
__device__ __forceinline__ void cpasync16(uint32_t dst, const void* src){
    asm volatile("cp.async.cg.shared.global [%0], [%1], 16;" :: "r"(dst), "l"(src));
}
#define CP_COMMIT() asm volatile("cp.async.commit_group;" ::: "memory")
#define CP_WAIT1()  asm volatile("cp.async.wait_group 1;" ::: "memory")
#define CP_WAIT0()  asm volatile("cp.async.wait_group 0;" ::: "memory")

#define LOG2E 1.4426950408889634f
#define SCL2E 0.1803368801111437f   /* 0.125 * log2(e) */

// ============================ convert X -> fp16 ============================
__global__ __launch_bounds__(256) void convert_x(const float* __restrict__ X){
    int i = (blockIdx.x * 256 + threadIdx.x) * 4;
    float4 v = *(const float4*)(X + i);
    uint2 u;
    u.x = packh2(v.x, v.y);
    u.y = packh2(v.z, v.w);
    *(uint2*)&g_xh[i] = u;
}

// ============================ convert W -> W^T fp16 ============================
__global__ __launch_bounds__(256) void convert_w(
    const float* __restrict__ Wq, const float* __restrict__ Wk, const float* __restrict__ Wv)
{
    __shared__ float t[32][33];
    const int z = blockIdx.z;
    const float* W = (z==0) ? Wq : (z==1) ? Wk : Wv;
    __half* out = g_wt + (size_t)z * D_ * D_;
    const int n0 = blockIdx.x * 32, k0 = blockIdx.y * 32;
    const int tx = threadIdx.x, ty = threadIdx.y;   // 32 x 8
#pragma unroll
    for (int i = 0; i < 32; i += 8)
        t[ty + i][tx] = W[(size_t)(k0 + ty + i) * D_ + n0 + tx];
    __syncthreads();
#pragma unroll
    for (int i = 0; i < 32; i += 8)
        out[(size_t)(n0 + ty + i) * D_ + k0 + tx] = __float2half_rn(t[tx][ty + i]);
}

// ============================ QKV GEMM (fp16 mma.sync, 3-stage cp.async) ============================
// block tile M=128 x N=128 (2 heads), K loop 768 in chunks of 64, 3-stage ring.
// 8 warps: 4(m) x 2(n), warp tile 32x64. 2 CTAs/SM (reg cap 128).
#define GEMM_SMEM 98304

__global__ __launch_bounds__(256, 2) void qkv_gemm_h(
    const float* __restrict__ bq, const float* __restrict__ bk, const float* __restrict__ bv)
{
    extern __shared__ char sm[];
    const uint32_t sA = smem_u32(sm);            // 3 x 16KB
    const uint32_t sB = sA + 49152;              // 3 x 16KB

    const int tid = threadIdx.x, wid = tid >> 5, lane = tid & 31;
    const int z  = blockIdx.z;
    const int m0 = blockIdx.x * 128;
    const int n0 = blockIdx.y * 128;

    const __half* Wth = g_wt + (size_t)z * D_ * D_;
    const float* bias = (z==0) ? bq : (z==1) ? bk : bv;
    __half* dst = (z==0) ? g_qh : (z==1) ? g_kh : g_vh;

    const int ar = tid >> 1, aseg = (tid & 1) * 4;   // row 0..127, 4 lines of 16B

    const int wm = wid & 3, wn = wid >> 2;
    const int lrow = lane & 15, lkhi = (lane >> 4) * 16;
    const int b_n  = (lane >> 4) * 8 + (lane & 7);
    const int b_k16 = ((lane >> 3) & 1) * 16;

    float acc[2][8][4];
#pragma unroll
    for (int i = 0; i < 2; i++)
#pragma unroll
        for (int j = 0; j < 8; j++)
#pragma unroll
            for (int c = 0; c < 4; c++) acc[i][j][c] = 0.0f;

    const __half* asrc_base = g_xh + (size_t)(m0 + ar) * D_ + aseg * 8;
    const __half* bsrc_base = Wth + (size_t)(n0 + ar) * D_ + aseg * 8;

    // prologue: stages 0,1
#pragma unroll
    for (int p = 0; p < 2; p++) {
        const int k0 = p * 64;
        const uint32_t so = p * 16384;
#pragma unroll
        for (int q = 0; q < 4; q++) {
            uint32_t byte = SWZ((uint32_t)ar * 128u + (aseg + q) * 16u);
            cpasync16(sA + so + byte, asrc_base + k0 + q * 8);
            cpasync16(sB + so + byte, bsrc_base + k0 + q * 8);
        }
        CP_COMMIT();
    }

    for (int kt = 0; kt < 12; kt++) {
        if (kt < 11) CP_WAIT1(); else CP_WAIT0();
        __syncthreads();
        if (kt + 2 < 12) {
            const int k0 = (kt + 2) * 64;
            const uint32_t so = ((kt + 2) % 3) * 16384;
#pragma unroll
            for (int q = 0; q < 4; q++) {
                uint32_t byte = SWZ((uint32_t)ar * 128u + (aseg + q) * 16u);
                cpasync16(sA + so + byte, asrc_base + k0 + q * 8);
                cpasync16(sB + so + byte, bsrc_base + k0 + q * 8);
            }
            CP_COMMIT();
        }

        const uint32_t a_base = sA + (kt % 3) * 16384;
        const uint32_t b_base = sB + (kt % 3) * 16384;
#pragma unroll
        for (int ks = 0; ks < 4; ks++) {
            uint32_t a0[4], a1[4];
            ldsm4(a0, a_base + SWZ((uint32_t)(wm*32 + lrow) * 128u + ks*32 + lkhi));
            ldsm4(a1, a_base + SWZ((uint32_t)(wm*32 + 16 + lrow) * 128u + ks*32 + lkhi));
#pragma unroll
            for (int jp = 0; jp < 4; jp++) {
                uint32_t bb[4];
                ldsm4(bb, b_base + SWZ((uint32_t)(wn*64 + jp*16 + b_n) * 128u + ks*32 + b_k16));
                mma16816(acc[0][jp*2+0], a0, bb+0);
                mma16816(acc[0][jp*2+1], a0, bb+2);
                mma16816(acc[1][jp*2+0], a1, bb+0);
                mma16816(acc[1][jp*2+1], a1, bb+2);
            }
        }
    }

    // epilogue: bias add, write head-major fp16
    const int g = lane >> 2, c2 = (lane & 3) * 2;
    const int h = (n0 >> 6) + wn;                    // warp's 64-col span = one head
#pragma unroll
    for (int i = 0; i < 2; i++) {
#pragma unroll
        for (int j = 0; j < 8; j++) {
            int col = j * 8 + c2;                    // dh within head
            float bz0 = bias[h * 64 + col], bz1 = bias[h * 64 + col + 1];
            int row = m0 + wm * 32 + i * 16 + g;
            int bb = row >> 11, ss = row & 2047;
            *(__half2*)&dst[(((size_t)bb * H_ + h) * S_ + ss) * HD_ + col] =
                __floats2half2_rn(acc[i][j][0] + bz0, acc[i][j][1] + bz1);
            row += 8; bb = row >> 11; ss = row & 2047;
            *(__half2*)&dst[(((size_t)bb * H_ + h) * S_ + ss) * HD_ + col] =
                __floats2half2_rn(acc[i][j][2] + bz0, acc[i][j][3] + bz1);
        }
    }
}

// ============================ attention (fp16 mma.sync, key-split warp groups) ============================
// block: one (b,h), 128 queries, 512 threads = 16 warps = 2 key-groups x 8 q-warps.
// Each warp: 16 q rows x 64 keys (its group's half of each 128-key tile).
// K/V smem bytes are read by 4 warps instead of 8 -> ldmatrix traffic halved.
// 2-stage cp.async ring. End: cross-group O / lsum reduction via smem.
// smem: Q@0 16KB, K0@16384, K1@32768, V0@49152, V1@65536, mask0@81920, mask1@82432
#define ATT_SMEM 82944

__global__ __launch_bounds__(512, 1) void attn_h(
    const float* __restrict__ mask, float* __restrict__ out)
{
    extern __shared__ char sm[];
    const uint32_t sQ = smem_u32(sm);
    const uint32_t sK = sQ + 16384;
    const uint32_t sV = sQ + 49152;
    const uint32_t sM = sQ + 81920;

    const int tid = threadIdx.x, wid = tid >> 5, lane = tid & 31;
    const int wq = wid & 7;          // q-warp: rows wq*16..+15
    const int kg = wid >> 3;         // key group: keys kg*64..+63 of each tile
    const int bh = blockIdx.y;
    const int b  = bh / H_;
    const int h  = bh % H_;
    const int q0 = blockIdx.x * 128;

    const __half* Qg = g_qh + (size_t)bh * S_ * HD_;
    const __half* Kg = g_kh + (size_t)bh * S_ * HD_;
    const __half* Vg = g_vh + (size_t)bh * S_ * HD_;
    const float* mrow = mask + (size_t)b * S_;

    // load Q tile [128][64] swizzled (plain stores). 1024 16B-lines, 2 per thread.
#pragma unroll
    for (int t = 0; t < 2; t++) {
        int l = tid + t * 512;
        int row = l >> 3, seg = l & 7;
        uint4 v = *(const uint4*)(Qg + (size_t)(q0 + row) * HD_ + seg * 8);
        *(uint4*)(sm + SWZ((uint32_t)row * 128u + seg * 16u)) = v;
    }

    // prologue: stage 0 of K/V/mask
    {
#pragma unroll
        for (int t = 0; t < 2; t++) {
            int l = tid + t * 512;
            int row = l >> 3, seg = l & 7;
            uint32_t byte = SWZ((uint32_t)row * 128u + seg * 16u);
            cpasync16(sK + byte, Kg + (size_t)row * HD_ + seg * 8);
            cpasync16(sV + byte, Vg + (size_t)row * HD_ + seg * 8);
        }
        if (tid < 32) cpasync16(sM + tid * 16, mrow + tid * 4);
        CP_COMMIT();
    }
    __syncthreads();   // Q visible for ldmatrix

    const int lrow = lane & 15, lkhi = (lane >> 4) * 16;
    const int b_n  = (lane >> 4) * 8 + (lane & 7);
    const int b_k16 = ((lane >> 3) & 1) * 16;

    // Q fragments register-resident (warp owns rows wq*16..+15)
    uint32_t qf[4][4];
#pragma unroll
    for (int ks = 0; ks < 4; ks++)
        ldsm4(qf[ks], sQ + SWZ((uint32_t)(wq*16 + lrow) * 128u + ks*32 + lkhi));

    float o[8][4];
#pragma unroll
    for (int j = 0; j < 8; j++)
#pragma unroll
        for (int c = 0; c < 4; c++) o[j][c] = 0.0f;
    float lsum0 = 0.0f, lsum1 = 0.0f;

    const int g = lane >> 2, c2 = (lane & 3) * 2;

    for (int kt = 0; kt < 16; kt++) {
        const int s = kt & 1;
        if (kt < 15) {
            const uint32_t so = (s ^ 1) * 16384;
#pragma unroll
            for (int t = 0; t < 2; t++) {
                int l = tid + t * 512;
                int row = l >> 3, seg = l & 7;
                uint32_t byte = SWZ((uint32_t)row * 128u + seg * 16u);
                cpasync16(sK + so + byte, Kg + (size_t)((kt+1)*128 + row) * HD_ + seg * 8);
                cpasync16(sV + so + byte, Vg + (size_t)((kt+1)*128 + row) * HD_ + seg * 8);
            }
            if (tid < 32) cpasync16(sM + (s ^ 1) * 512 + tid * 16, mrow + (kt+1)*128 + tid * 4);
            CP_COMMIT();
            CP_WAIT1();
        } else {
            CP_WAIT0();
        }
        __syncthreads();

        const uint32_t kb = sK + s * 16384;
        const uint32_t vb = sV + s * 16384;
        const float* maskS = (const float*)(sm + 81920 + s * 512);

        // two 32-key half-passes over this warp's 64 keys
#pragma unroll
        for (int hf = 0; hf < 2; hf++) {
            const int kbase = kg * 64 + hf * 32;

            // scores for 32 keys: 4 n8-tiles
            float sc[4][4];
#pragma unroll
            for (int t = 0; t < 4; t++)
#pragma unroll
                for (int c = 0; c < 4; c++) sc[t][c] = 0.0f;

#pragma unroll
            for (int ks = 0; ks < 4; ks++) {
#pragma unroll
                for (int jp = 0; jp < 2; jp++) {
                    uint32_t bb[4];
                    ldsm4(bb, kb + SWZ((uint32_t)(kbase + jp*16 + b_n) * 128u + ks*32 + b_k16));
                    mma16816(sc[jp*2+0], qf[ks], bb+0);
                    mma16816(sc[jp*2+1], qf[ks], bb+2);
                }
            }

            // softmax (no max subtraction): p = exp2(s*0.125*log2e + m*log2e)
            uint32_t pf[2][4];
#pragma unroll
            for (int jp = 0; jp < 2; jp++) {
                float pe[4], po[4];
                {
                    int tt = jp * 2;
                    float m0v = maskS[kbase + tt*8 + c2] * LOG2E;
                    float m1v = maskS[kbase + tt*8 + c2 + 1] * LOG2E;
                    pe[0] = ex2(fmaf(sc[tt][0], SCL2E, m0v));
                    pe[1] = ex2(fmaf(sc[tt][1], SCL2E, m1v));
                    pe[2] = ex2(fmaf(sc[tt][2], SCL2E, m0v));
                    pe[3] = ex2(fmaf(sc[tt][3], SCL2E, m1v));
                }
                {
                    int tt = jp * 2 + 1;
                    float m0v = maskS[kbase + tt*8 + c2] * LOG2E;
                    float m1v = maskS[kbase + tt*8 + c2 + 1] * LOG2E;
                    po[0] = ex2(fmaf(sc[tt][0], SCL2E, m0v));
                    po[1] = ex2(fmaf(sc[tt][1], SCL2E, m1v));
                    po[2] = ex2(fmaf(sc[tt][2], SCL2E, m0v));
                    po[3] = ex2(fmaf(sc[tt][3], SCL2E, m1v));
                }
                lsum0 += pe[0] + pe[1] + po[0] + po[1];
                lsum1 += pe[2] + pe[3] + po[2] + po[3];
                pf[jp][0] = packh2(pe[0], pe[1]);
                pf[jp][1] = packh2(pe[2], pe[3]);
                pf[jp][2] = packh2(po[0], po[1]);
                pf[jp][3] = packh2(po[2], po[3]);
            }

            // O += P_half @ V_half : 2 k16 steps over these 32 keys, 8 d-tiles
#pragma unroll
            for (int ks2 = 0; ks2 < 2; ks2++) {
#pragma unroll
                for (int pp = 0; pp < 4; pp++) {
                    uint32_t bb[4];
                    uint32_t key = (uint32_t)(kbase + ks2*16 + ((lane>>3)&1)*8 + (lane&7));
                    uint32_t byte = (uint32_t)(2*pp + (lane>>4)) * 16u;
                    ldsm4t(bb, vb + SWZ(key * 128u + byte));
                    mma16816(o[pp*2+0], pf[ks2], bb+0);
                    mma16816(o[pp*2+1], pf[ks2], bb+2);
                }
            }
        }
        __syncthreads();   // everyone done with stage s before it is refilled
    }

    // reduce row sums across the 4-thread quad (within this warp's 64 keys)
    lsum0 += __shfl_xor_sync(0xffffffffu, lsum0, 1);
    lsum0 += __shfl_xor_sync(0xffffffffu, lsum0, 2);
    lsum1 += __shfl_xor_sync(0xffffffffu, lsum1, 1);
    lsum1 += __shfl_xor_sync(0xffffffffu, lsum1, 2);

    // cross-group reduction via smem (reuse dead K/V stage region)
    float* stageO = (float*)(sm + 16384);          // [128][66] f32
    float* lred   = (float*)(sm + 16384 + 33792);  // [128] f32
    const int r0 = wq * 16 + g;

    __syncthreads();   // all reads of K/V stages complete before overwrite
    if (kg == 1) {
#pragma unroll
        for (int j = 0; j < 8; j++) {
            int col = j * 8 + c2;
            stageO[r0 * 66 + col]       = o[j][0];
            stageO[r0 * 66 + col + 1]   = o[j][1];
            stageO[(r0+8) * 66 + col]     = o[j][2];
            stageO[(r0+8) * 66 + col + 1] = o[j][3];
        }
        if ((lane & 3) == 0) { lred[r0] = lsum0; lred[r0 + 8] = lsum1; }
    }
    __syncthreads();

    if (kg == 0) {
        const float inv0 = 1.0f / (lsum0 + lred[r0]);
        const float inv1 = 1.0f / (lsum1 + lred[r0 + 8]);
        float* out0 = out + ((size_t)b * S_ + q0 + r0) * D_ + h * HD_;
        float* out1 = out + ((size_t)b * S_ + q0 + r0 + 8) * D_ + h * HD_;
#pragma unroll
        for (int j = 0; j < 8; j++) {
            int d = j * 8 + c2;
            float2 v0 = make_float2((o[j][0] + stageO[r0*66 + d]) * inv0,
                                    (o[j][1] + stageO[r0*66 + d + 1]) * inv0);
            float2 v1 = make_float2((o[j][2] + stageO[(r0+8)*66 + d]) * inv1,
                                    (o[j][3] + stageO[(r0+8)*66 + d + 1]) * inv1);
            *(float2*)&out0[d] = v0;
            *(float2*)&out1[d] = v1;
        }
    }
}

// ============================ launch ============================
extern "C" void kernel_launch(void* const* d_in, const int* in_sizes, int n_in,
                              void* d_out, int out_size)
{
    const float* v1   = (const float*)d_in[0];
    const float* mask = (const float*)d_in[1];
    const float* Wq   = (const float*)d_in[2];
    const float* bq   = (const float*)d_in[3];
    const float* Wk   = (const float*)d_in[4];
    const float* bk   = (const float*)d_in[5];
    const float* Wv   = (const float*)d_in[6];
    const float* bv   = (const float*)d_in[7];
    float* out = (float*)d_out;

    convert_x<<<NTOK * D_ / 1024, 256>>>(v1);
    convert_w<<<dim3(D_/32, D_/32, 3), dim3(32, 8)>>>(Wq, Wk, Wv);

    cudaFuncSetAttribute(qkv_gemm_h, cudaFuncAttributeMaxDynamicSharedMemorySize, GEMM_SMEM);
    qkv_gemm_h<<<dim3(NTOK/128, D_/128, 3), 256, GEMM_SMEM>>>(bq, bk, bv);

    cudaFuncSetAttribute(attn_h, cudaFuncAttributeMaxDynamicSharedMemorySize, ATT_SMEM);
    attn_h<<<dim3(S_/128, B_*H_), 512, ATT_SMEM>>>(mask, out);
}